// round 4
// baseline (speedup 1.0000x reference)
#include <cuda_runtime.h>
#include <cuda_bf16.h>

// One CTA per 64x64 image, 256 threads.
// Thread t: col quad q = t&15 (cols 4q..4q+3), rows 4*(t>>4)..+3.
// Direct global reads (L2-resident), halo via warp shuffle.
// Conv in PACKED fp32 (fma.rn.f32x2): 2 pixels per op.
// |gx|+|gy| == max(|conv(S)|, |conv(D)|), S=wr+wr^T, D=wr-wr^T.

#define FULL 0xffffffffu
#define NUM_IMG 2048

typedef unsigned long long u64;

__device__ __forceinline__ u64 pack2(float lo, float hi) {
    u64 d;
    asm("mov.b64 %0, {%1, %2};" : "=l"(d) : "r"(__float_as_uint(lo)), "r"(__float_as_uint(hi)));
    return d;
}
__device__ __forceinline__ void unpack2(u64 d, float& lo, float& hi) {
    unsigned a, b;
    asm("mov.b64 {%0, %1}, %2;" : "=r"(a), "=r"(b) : "l"(d));
    lo = __uint_as_float(a); hi = __uint_as_float(b);
}
__device__ __forceinline__ u64 fma2(u64 a, u64 b, u64 c) {
    u64 d; asm("fma.rn.f32x2 %0, %1, %2, %3;" : "=l"(d) : "l"(a), "l"(b), "l"(c)); return d;
}
__device__ __forceinline__ u64 mul2(u64 a, u64 b) {
    u64 d; asm("mul.rn.f32x2 %0, %1, %2;" : "=l"(d) : "l"(a), "l"(b)); return d;
}
__device__ __forceinline__ u64 add2(u64 a, u64 b) {
    u64 d; asm("add.rn.f32x2 %0, %1, %2;" : "=l"(d) : "l"(a), "l"(b)); return d;
}

__global__ __launch_bounds__(256)
void sobel_norm_kernel(const float* __restrict__ in,
                       const float* __restrict__ w,
                       const float* __restrict__ wf,
                       const float* __restrict__ scale_p,
                       float* __restrict__ out) {
    __shared__ float smin[8];
    __shared__ float smax[8];

    const int img = blockIdx.x;
    const int tid = threadIdx.x;
    const int q   = tid & 15;        // col quad 0..15
    const int r0  = (tid >> 4) << 2; // first output row
    const int c0  = q << 2;          // first output col

    // --- weights: clip, scale, sym/antisym split, packed broadcast ---
    const float f = fminf(fmaxf(wf[0], 1.0f), 255.0f);
    float wr[9];
#pragma unroll
    for (int i = 0; i < 9; i++)
        wr[i] = fminf(fmaxf(__ldg(w + i), -1.0f), 1.0f) * f;
    const u64 s00p = pack2(wr[0] + wr[0], wr[0] + wr[0]);
    const u64 s11p = pack2(wr[4] + wr[4], wr[4] + wr[4]);
    const u64 s22p = pack2(wr[8] + wr[8], wr[8] + wr[8]);
    const u64 s01p = pack2(wr[1] + wr[3], wr[1] + wr[3]);
    const u64 s02p = pack2(wr[2] + wr[6], wr[2] + wr[6]);
    const u64 s12p = pack2(wr[5] + wr[7], wr[5] + wr[7]);
    const u64 d01p = pack2(wr[1] - wr[3], wr[1] - wr[3]);
    const u64 d02p = pack2(wr[2] - wr[6], wr[2] - wr[6]);
    const u64 d12p = pack2(wr[5] - wr[7], wr[5] - wr[7]);
    const u64 NEG1 = 0xBF800000BF800000ULL;   // {-1.0f, -1.0f}

    const float* __restrict__ base = in + (size_t)img * 4096 + c0;

    // Sliding 3-row window, each row as 5 packed pairs {V[k],V[k+1]}, V = cols c0-1..c0+4
    u64 W[3][5];

    auto load_row = [&](int j, u64* P) {
        float4 m = make_float4(0.f, 0.f, 0.f, 0.f);
        if ((unsigned)j < 64u)
            m = *reinterpret_cast<const float4*>(base + (j << 6));
        float lf = __shfl_up_sync(FULL, m.w, 1);
        float rg = __shfl_down_sync(FULL, m.x, 1);
        if (q == 0)  lf = 0.f;
        if (q == 15) rg = 0.f;
        P[0] = pack2(lf,  m.x);
        P[1] = pack2(m.x, m.y);
        P[2] = pack2(m.y, m.z);
        P[3] = pack2(m.z, m.w);
        P[4] = pack2(m.w, rg);
    };

    load_row(r0 - 1, W[0]);
    load_row(r0,     W[1]);

    float g[16];
    float gmn = 3.4e38f;
    float gmx = 0.0f;   // g >= 0

#pragma unroll
    for (int i = 0; i < 4; i++) {
        load_row(r0 + 1 + i, W[(i + 2) % 3]);
        const u64* A = W[i % 3];           // top
        const u64* B = W[(i + 1) % 3];     // mid
        const u64* C = W[(i + 2) % 3];     // bot
#pragma unroll
        for (int h = 0; h < 2; h++) {      // pixel pairs (2h, 2h+1)
            const int j = h << 1;
            // S = conv(wr + wr^T) = gx + gy
            u64 t01 = add2(A[j + 1], B[j]);
            u64 t02 = add2(A[j + 2], C[j]);
            u64 t12 = add2(B[j + 2], C[j + 1]);
            u64 S = mul2(s00p, A[j]);
            S = fma2(s11p, B[j + 1], S);
            S = fma2(s22p, C[j + 2], S);
            S = fma2(s01p, t01, S);
            S = fma2(s02p, t02, S);
            S = fma2(s12p, t12, S);
            // D = conv(wr - wr^T) = gx - gy (diagonal vanishes); subs via exact fma(x,-1,y)
            u64 u01 = fma2(B[j],     NEG1, A[j + 1]);
            u64 u02 = fma2(C[j],     NEG1, A[j + 2]);
            u64 u12 = fma2(C[j + 1], NEG1, B[j + 2]);
            u64 D = mul2(d01p, u01);
            D = fma2(d02p, u02, D);
            D = fma2(d12p, u12, D);
            // |gx|+|gy| = max(|S|,|D|) per lane
            float s0, s1, e0, e1;
            unpack2(S, s0, s1);
            unpack2(D, e0, e1);
            const float g0 = fmaxf(fabsf(s0), fabsf(e0));
            const float g1 = fmaxf(fabsf(s1), fabsf(e1));
            g[i * 4 + j]     = g0;
            g[i * 4 + j + 1] = g1;
            gmn = fminf(gmn, fminf(g0, g1));
            gmx = fmaxf(gmx, fmaxf(g0, g1));
        }
    }

    // --- block min/max reduction ---
#pragma unroll
    for (int o = 16; o; o >>= 1) {
        gmn = fminf(gmn, __shfl_xor_sync(FULL, gmn, o));
        gmx = fmaxf(gmx, __shfl_xor_sync(FULL, gmx, o));
    }
    if ((tid & 31) == 0) { smin[tid >> 5] = gmn; smax[tid >> 5] = gmx; }
    __syncthreads();
    gmn = smin[0]; gmx = smax[0];
#pragma unroll
    for (int i = 1; i < 8; i++) {
        gmn = fminf(gmn, smin[i]);
        gmx = fmaxf(gmx, smax[i]);
    }

    const float mul = 255.0f / fmaxf(gmx - gmn, 1.0f);
    const float nb  = -gmn * mul;
    const float isc = 1.0f / scale_p[0];

    // --- normalize + floor + scale; float4 stores ---
    float* __restrict__ op = out + (size_t)img * 4096 + (r0 << 6) + c0;
#pragma unroll
    for (int i = 0; i < 4; i++) {
        float4 o4;
        o4.x = floorf(fmaf(g[i * 4 + 0], mul, nb)) * isc;
        o4.y = floorf(fmaf(g[i * 4 + 1], mul, nb)) * isc;
        o4.z = floorf(fmaf(g[i * 4 + 2], mul, nb)) * isc;
        o4.w = floorf(fmaf(g[i * 4 + 3], mul, nb)) * isc;
        *reinterpret_cast<float4*>(op + (i << 6)) = o4;
    }
}

extern "C" void kernel_launch(void* const* d_in, const int* in_sizes, int n_in,
                              void* d_out, int out_size) {
    const float* in      = (const float*)d_in[0];  // (2048,1,64,64) fp32
    const float* w       = (const float*)d_in[1];  // (1,9) fp32
    const float* wf      = (const float*)d_in[2];  // (1,) fp32
    const float* scale_p = (const float*)d_in[3];  // (1,1) fp32
    float* out = (float*)d_out;                    // (1,2048,1,64,64) fp32
    (void)in_sizes; (void)n_in; (void)out_size;

    sobel_norm_kernel<<<NUM_IMG, 256>>>(in, w, wf, scale_p, out);
}

// round 5
// speedup vs baseline: 1.0156x; 1.0156x over previous
#include <cuda_runtime.h>
#include <cuda_bf16.h>

// One CTA per 64x64 image, 256 threads.
// Thread t: col quad q = t&15 (cols 4q..4q+3), rows 4*(t>>4)..+3.
// Direct global reads (L2-resident) as float4; L/R halo via warp shuffle.
// |gx|+|gy| == max(|conv(S)|, |conv(D)|), S=wr+wr^T, D=wr-wr^T.
// g values parked in smem (conflict-free) to cut regs -> 6 CTAs/SM.

#define FULL 0xffffffffu
#define NUM_IMG 2048

__global__ __launch_bounds__(256, 6)
void sobel_norm_kernel(const float* __restrict__ in,
                       const float* __restrict__ w,
                       const float* __restrict__ wf,
                       const float* __restrict__ scale_p,
                       float* __restrict__ out) {
    __shared__ float sg[16][256];   // 16 KB: per-thread g values, [i][tid] -> conflict-free
    __shared__ float smin[8];
    __shared__ float smax[8];

    const int img = blockIdx.x;
    const int tid = threadIdx.x;
    const int q   = tid & 15;        // col quad 0..15
    const int r0  = (tid >> 4) << 2; // first output row (0..60)
    const int c0  = q << 2;          // first output col

    const float* __restrict__ base = in + (size_t)img * 4096 + c0;

    // --- weights: clip, scale, sym/antisym split ---
    const float f = fminf(fmaxf(wf[0], 1.0f), 255.0f);
    float wr[9];
#pragma unroll
    for (int i = 0; i < 9; i++)
        wr[i] = fminf(fmaxf(__ldg(w + i), -1.0f), 1.0f) * f;
    const float s00 = wr[0] + wr[0];
    const float s11 = wr[4] + wr[4];
    const float s22 = wr[8] + wr[8];
    const float s01 = wr[1] + wr[3];
    const float s02 = wr[2] + wr[6];
    const float s12 = wr[5] + wr[7];
    const float d01 = wr[1] - wr[3];
    const float d02 = wr[2] - wr[6];
    const float d12 = wr[5] - wr[7];

    // Sliding 3-row window; each row is 6 floats: cols c0-1 .. c0+4.
    float W[3][6];

    // halo assembly from a loaded float4
    auto spread = [&](float4 m, float* V) {
        float lf = __shfl_up_sync(FULL, m.w, 1);
        float rg = __shfl_down_sync(FULL, m.x, 1);
        if (q == 0)  lf = 0.f;
        if (q == 15) rg = 0.f;
        V[0] = lf;
        V[1] = m.x; V[2] = m.y; V[3] = m.z; V[4] = m.w;
        V[5] = rg;
    };
    auto load_row_guard = [&](int j, float* V) {   // j may be out of [0,64)
        float4 m = make_float4(0.f, 0.f, 0.f, 0.f);
        if ((unsigned)j < 64u)
            m = *reinterpret_cast<const float4*>(base + (j << 6));
        spread(m, V);
    };
    auto load_row = [&](int j, float* V) {         // j guaranteed in bounds
        spread(*reinterpret_cast<const float4*>(base + (j << 6)), V);
    };

    load_row_guard(r0 - 1, W[0]);
    load_row(r0, W[1]);

    float gmn = 3.4e38f;
    float gmx = 0.0f;   // g >= 0

#pragma unroll
    for (int i = 0; i < 4; i++) {
        if (i < 3) load_row(r0 + 1 + i, W[(i + 2) % 3]);
        else       load_row_guard(r0 + 4, W[(i + 2) % 3]);
        const float* a = W[i % 3];           // top
        const float* b = W[(i + 1) % 3];     // mid
        const float* c = W[(i + 2) % 3];     // bot
#pragma unroll
        for (int p = 0; p < 4; p++) {
            const float a0 = a[p], a1 = a[p + 1], a2 = a[p + 2];
            const float b0 = b[p], b1 = b[p + 1], b2 = b[p + 2];
            const float c1 = c[p], c2 = c[p + 1], c3 = c[p + 2];
            // S = conv(wr + wr^T) = gx + gy
            float S = s00 * a0;
            S = fmaf(s11, b1, S);
            S = fmaf(s22, c3, S);
            S = fmaf(s01, a1 + b0, S);
            S = fmaf(s02, a2 + c1, S);
            S = fmaf(s12, b2 + c2, S);
            // D = conv(wr - wr^T) = gx - gy  (diagonal vanishes)
            float D = d01 * (a1 - b0);
            D = fmaf(d02, a2 - c1, D);
            D = fmaf(d12, b2 - c2, D);
            // |gx| + |gy| = max(|S|, |D|)
            const float gv = fmaxf(fabsf(S), fabsf(D));
            sg[i * 4 + p][tid] = gv;
            gmn = fminf(gmn, gv);
            gmx = fmaxf(gmx, gv);
        }
    }

    // --- block min/max reduction ---
#pragma unroll
    for (int o = 16; o; o >>= 1) {
        gmn = fminf(gmn, __shfl_xor_sync(FULL, gmn, o));
        gmx = fmaxf(gmx, __shfl_xor_sync(FULL, gmx, o));
    }
    if ((tid & 31) == 0) { smin[tid >> 5] = gmn; smax[tid >> 5] = gmx; }
    __syncthreads();
    gmn = smin[0]; gmx = smax[0];
#pragma unroll
    for (int i = 1; i < 8; i++) {
        gmn = fminf(gmn, smin[i]);
        gmx = fmaxf(gmx, smax[i]);
    }

    const float mul = 255.0f / fmaxf(gmx - gmn, 1.0f);
    const float isc = 1.0f / scale_p[0];

    // --- normalize + floor + scale; float4 stores ---
    float* __restrict__ op = out + (size_t)img * 4096 + (r0 << 6) + c0;
#pragma unroll
    for (int i = 0; i < 4; i++) {
        float4 o4;
        o4.x = floorf((sg[i * 4 + 0][tid] - gmn) * mul) * isc;
        o4.y = floorf((sg[i * 4 + 1][tid] - gmn) * mul) * isc;
        o4.z = floorf((sg[i * 4 + 2][tid] - gmn) * mul) * isc;
        o4.w = floorf((sg[i * 4 + 3][tid] - gmn) * mul) * isc;
        *reinterpret_cast<float4*>(op + (i << 6)) = o4;
    }
}

extern "C" void kernel_launch(void* const* d_in, const int* in_sizes, int n_in,
                              void* d_out, int out_size) {
    const float* in      = (const float*)d_in[0];  // (2048,1,64,64) fp32
    const float* w       = (const float*)d_in[1];  // (1,9) fp32
    const float* wf      = (const float*)d_in[2];  // (1,) fp32
    const float* scale_p = (const float*)d_in[3];  // (1,1) fp32
    float* out = (float*)d_out;                    // (1,2048,1,64,64) fp32
    (void)in_sizes; (void)n_in; (void)out_size;

    sobel_norm_kernel<<<NUM_IMG, 256>>>(in, w, wf, scale_p, out);
}